// round 7
// baseline (speedup 1.0000x reference)
#include <cuda_runtime.h>
#include <cstdint>
#include <cstddef>

#define D 128
#define G 100
#define NIN 5          // INPUT_DIM
#define BE 128         // edges per tile
#define NMAX 20000
#define EMAX 320000
#define LOG2F_ 0.6931471805599453f

// ---------------- device scratch (no allocation allowed) ----------------
__device__ __align__(256) float g_h [NMAX * D];
__device__ __align__(256) float g_xf[NMAX * D];
__device__ __align__(256) float g_mi[NMAX * D];
__device__ __align__(256) float g_m [NMAX * D];
__device__ __align__(256) int   g_src[EMAX];
__device__ __align__(256) int   g_dst[EMAX];
__device__ int g_is64;

typedef unsigned long long u64;

// packed fp32x2 FMA (sm_100+): c = a*b + c on both lanes
__device__ __forceinline__ void fma2(u64 &c, u64 a, u64 b) {
    asm("fma.rn.f32x2 %0, %1, %2, %0;" : "+l"(c) : "l"(a), "l"(b));
}
__device__ __forceinline__ u64 pack2same(float w) {
    u64 r; asm("mov.b64 %0, {%1, %1};" : "=l"(r) : "f"(w)); return r;
}
__device__ __forceinline__ float2 unpack2(u64 v) {
    float2 r; asm("mov.b64 {%0, %1}, %2;" : "=f"(r.x), "=f"(r.y) : "l"(v)); return r;
}
// shifted softplus: log(1+e^x) - log(2), numerically stable
__device__ __forceinline__ float sspf(float x) {
    return fmaxf(x, 0.0f) + log1pf(__expf(-fabsf(x))) - LOG2F_;
}

// =======================================================================
// edge_index dtype detection: values are in [0, N) << 2^31. If the buffer
// is int64 (little-endian), every odd 32-bit word (high half) is 0. If it
// is int32, odd words are random indices -> virtually never all zero.
// =======================================================================
__global__ void detect_kernel(const int* __restrict__ w)
{
    __shared__ int s_or;
    if (threadIdx.x == 0) s_or = 0;
    __syncthreads();
    int v = 0;
    for (int i = threadIdx.x; i < 1024; i += 256) v |= w[2 * i + 1];
    if (v) atomicOr(&s_or, 1);
    __syncthreads();
    if (threadIdx.x == 0) g_is64 = (s_or == 0) ? 1 : 0;
}

// Unpack + bounds-clamp indices into int32 arrays (crash-proof either way)
__global__ void convert_idx_kernel(const void* __restrict__ ei, int E_, int N_)
{
    int e = blockIdx.x * blockDim.x + threadIdx.x;
    if (e >= E_) return;
    long long s, d;
    if (g_is64) {
        const long long* p = (const long long*)ei;
        s = p[e]; d = p[E_ + e];
    } else {
        const int* p = (const int*)ei;
        s = p[e]; d = p[E_ + e];
    }
    g_src[e] = (s >= 0 && s < N_) ? (int)s : 0;
    g_dst[e] = (d >= 0 && d < N_) ? (int)d : 0;
}

// =======================================================================
// Embedding: h = zf @ emblin_w.T + emblin_b + ptemb
// =======================================================================
__global__ void embed_kernel(const float* __restrict__ z,
                             const float* __restrict__ ew,
                             const float* __restrict__ eb,
                             float* __restrict__ h, int N_)
{
    int i = blockIdx.x * blockDim.x + threadIdx.x;
    if (i >= N_ * D) return;
    int n = i >> 7, d = i & 127;
    const float* zr = z + (size_t)n * (NIN + D);
    float acc = eb[d] + zr[NIN + d];
#pragma unroll
    for (int k = 0; k < NIN; k++) acc = fmaf(zr[k], ew[d * NIN + k], acc);
    h[i] = acc;
}

__global__ void zero_kernel(float* __restrict__ p, int n)
{
    int i = blockIdx.x * blockDim.x + threadIdx.x;
    if (i < n) p[i] = 0.0f;
}

// =======================================================================
// Edge kernel (persistent): per 128-edge tile:
//   T  = ssp(EA @ W1.T + b1)            (K = 100)
//   Wf = (T @ W2.T + b2) * C            (K = 128)
//   m_i[dst] += xf[src] * Wf            (float4 atomics)
// Thread tile: 8 edges x 8 outputs, packed f32x2 over edge pairs.
// =======================================================================
__global__ __launch_bounds__(256, 1)
void edge_kernel(const float* __restrict__ edge_attr,
                 const int* __restrict__ esrc,
                 const int* __restrict__ edst,
                 const float* __restrict__ edge_length,
                 const float* __restrict__ w1, const float* __restrict__ b1,
                 const float* __restrict__ w2, const float* __restrict__ b2,
                 const float* __restrict__ xf, float* __restrict__ mi,
                 int E_)
{
    extern __shared__ float sm[];
    float* W1t = sm;                 // [100][128]           12800 f
    float* W2t = W1t + G * D;        // [128][128]           16384 f
    float* U   = W2t + D * D;        // union, 128 x 132     16896 f
    float* B1  = U + BE * 132;       // 128 f
    float* B2  = B1 + D;             // 128 f
    float* CeS = B2 + D;             // 128 f
    int*   srcS = (int*)(CeS + BE);  // 128 i
    int*   dstS = srcS + BE;         // 128 i

    const int tid = threadIdx.x;
    const int tx  = tid & 15;        // output-d group: d = tx + 16*j
    const int ty  = tid >> 4;        // edge group of 8: e = 8*ty + {0..7}
    const int e0t = ty * 8;

    // load weights transposed (once per block)
    for (int idx = tid; idx < D * G; idx += 256) {
        int d = idx / G, g = idx - d * G;
        W1t[g * D + d] = w1[idx];
    }
    for (int idx = tid; idx < D * D; idx += 256) {
        int d = idx >> 7, k = idx & 127;
        W2t[k * D + d] = w2[idx];
    }
    if (tid < D) { B1[tid] = b1[tid]; B2[tid] = b2[tid]; }
    __syncthreads();

    const int ntiles = (E_ + BE - 1) / BE;
    for (int t = blockIdx.x; t < ntiles; t += gridDim.x) {
        const int ebase = t * BE;

        // edge metadata
        if (tid < BE) {
            int e = ebase + tid;
            if (e < E_) {
                srcS[tid] = esrc[e];
                dstS[tid] = edst[e];
                CeS[tid]  = (edge_length[e] <= 10.0f) ? 1.0f : 0.0f;
            } else {
                srcS[tid] = 0; dstS[tid] = 0; CeS[tid] = 0.0f;
            }
        }
        // EA tile transposed into U: U[g*128 + e]
        for (int idx = tid; idx < BE * G; idx += 256) {
            int e = idx / G, g = idx - e * G;
            int ge = ebase + e;
            U[g * BE + e] = (ge < E_) ? edge_attr[(size_t)ge * G + g] : 0.0f;
        }
        __syncthreads();

        // ---- GEMM1: K = 100 ----
        u64 acc[4][8];
#pragma unroll
        for (int p = 0; p < 4; p++)
#pragma unroll
            for (int j = 0; j < 8; j++) acc[p][j] = 0ull;

#pragma unroll 2
        for (int g = 0; g < G; g++) {
            const float* Ug = U + g * BE + e0t;
            u64 a[4];
#pragma unroll
            for (int p = 0; p < 4; p++) a[p] = *(const u64*)(Ug + 2 * p);
            const float* Wg = W1t + g * D + tx;
#pragma unroll
            for (int j = 0; j < 8; j++) {
                u64 wp = pack2same(Wg[16 * j]);
#pragma unroll
                for (int p = 0; p < 4; p++) fma2(acc[p][j], a[p], wp);
            }
        }
        __syncthreads();   // all reads of EA tile done

        // ssp + store T into U with row stride 132 (rows = k index)
#pragma unroll
        for (int j = 0; j < 8; j++) {
            int k = tx + 16 * j;
            float bb = B1[k];
            float* Ur = U + k * 132 + e0t;
#pragma unroll
            for (int p = 0; p < 4; p++) {
                float2 v = unpack2(acc[p][j]);
                Ur[2 * p]     = sspf(v.x + bb);
                Ur[2 * p + 1] = sspf(v.y + bb);
            }
        }
        __syncthreads();

        // ---- GEMM2: K = 128 ----
#pragma unroll
        for (int p = 0; p < 4; p++)
#pragma unroll
            for (int j = 0; j < 8; j++) acc[p][j] = 0ull;

#pragma unroll 2
        for (int k = 0; k < D; k++) {
            const float* Uk = U + k * 132 + e0t;
            u64 a[4];
#pragma unroll
            for (int p = 0; p < 4; p++) a[p] = *(const u64*)(Uk + 2 * p);
            const float* Wg = W2t + k * D + tx;
#pragma unroll
            for (int j = 0; j < 8; j++) {
                u64 wp = pack2same(Wg[16 * j]);
#pragma unroll
                for (int p = 0; p < 4; p++) fma2(acc[p][j], a[p], wp);
            }
        }
        __syncthreads();   // all reads of T done

        // Wf*C into U, now per-edge rows: U[e*132 + d]
#pragma unroll
        for (int j = 0; j < 8; j++) {
            int d = tx + 16 * j;
            float bb = B2[d];
#pragma unroll
            for (int p = 0; p < 4; p++) {
                float2 v = unpack2(acc[p][j]);
                int ea = e0t + 2 * p;
                U[ea * 132 + d]       = (v.x + bb) * CeS[ea];
                U[(ea + 1) * 132 + d] = (v.y + bb) * CeS[ea + 1];
            }
        }
        __syncthreads();

        // scatter: m_i[dst] += xf[src] * Wf   (float4 vector atomics)
        for (int idx = tid; idx < BE * (D / 4); idx += 256) {
            int e = idx >> 5;          // D/4 == 32
            int q = idx & 31;
            if (ebase + e < E_) {
                float4 wf = *(const float4*)(U + e * 132 + q * 4);
                int s = srcS[e], dd = dstS[e];
                float4 x4 = *(const float4*)(xf + (size_t)s * D + q * 4);
                float4 v;
                v.x = wf.x * x4.x; v.y = wf.y * x4.y;
                v.z = wf.z * x4.z; v.w = wf.w * x4.w;
                atomicAdd((float4*)(mi + (size_t)dd * D) + q, v);
            }
        }
        __syncthreads();
    }
}

// =======================================================================
// Node GEMM: out = act(in @ w.T [+ bias]); mode 0: plain, 1: bias+ssp
// Tile: 128 rows x 128 cols per block.
// =======================================================================
__global__ __launch_bounds__(256, 1)
void node_gemm_kernel(const float* __restrict__ in,
                      const float* __restrict__ w,     // [128][128] (out,in)
                      const float* __restrict__ bias,  // may be null
                      float* __restrict__ out,
                      int N_, int mode)
{
    extern __shared__ float sm[];
    float* Wt = sm;            // 16384 f
    float* Ht = Wt + D * D;    // 128 x 132

    const int tid = threadIdx.x;
    const int tx = tid & 15, ty = tid >> 4;
    const int e0t = ty * 8;
    const int n0 = blockIdx.x * 128;

    for (int idx = tid; idx < D * D; idx += 256) {
        int d = idx >> 7, k = idx & 127;
        Wt[k * D + d] = w[idx];
    }
    for (int idx = tid; idx < 128 * D; idx += 256) {
        int n = idx >> 7, k = idx & 127;
        Ht[k * 132 + n] = (n0 + n < N_) ? in[(size_t)(n0 + n) * D + k] : 0.0f;
    }
    __syncthreads();

    u64 acc[4][8];
#pragma unroll
    for (int p = 0; p < 4; p++)
#pragma unroll
        for (int j = 0; j < 8; j++) acc[p][j] = 0ull;

#pragma unroll 2
    for (int k = 0; k < D; k++) {
        const float* Uk = Ht + k * 132 + e0t;
        u64 a[4];
#pragma unroll
        for (int p = 0; p < 4; p++) a[p] = *(const u64*)(Uk + 2 * p);
        const float* Wg = Wt + k * D + tx;
#pragma unroll
        for (int j = 0; j < 8; j++) {
            u64 wp = pack2same(Wg[16 * j]);
#pragma unroll
            for (int p = 0; p < 4; p++) fma2(acc[p][j], a[p], wp);
        }
    }

#pragma unroll
    for (int j = 0; j < 8; j++) {
        int d = tx + 16 * j;
        float bb = bias ? bias[d] : 0.0f;
#pragma unroll
        for (int p = 0; p < 4; p++) {
            float2 v = unpack2(acc[p][j]);
            int n1 = n0 + e0t + 2 * p;
            if (n1 < N_) {
                float r = v.x + bb;
                out[(size_t)n1 * D + d] = mode ? sspf(r) : r;
            }
            if (n1 + 1 < N_) {
                float r = v.y + bb;
                out[(size_t)(n1 + 1) * D + d] = mode ? sspf(r) : r;
            }
        }
    }
}

// =======================================================================
// Update: h = h + concat([h, m]) @ lin_w.T + lin_b
//       = h + h @ lwA.T + m @ lwB.T + b   (two weight stages, one buffer)
// Optionally also writes out2 (final layer -> d_out).
// =======================================================================
__global__ __launch_bounds__(256, 1)
void update_kernel(float* __restrict__ h, const float* __restrict__ m,
                   const float* __restrict__ lw,   // [128][256]
                   const float* __restrict__ lb,
                   int N_, float* __restrict__ out2)
{
    extern __shared__ float sm[];
    float* Wt = sm;                  // 16384 f (reloaded per stage)
    float* Ht = Wt + D * D;          // 128 x 132
    float* Mt = Ht + 128 * 132;      // 128 x 132

    const int tid = threadIdx.x;
    const int tx = tid & 15, ty = tid >> 4;
    const int e0t = ty * 8;
    const int n0 = blockIdx.x * 128;

    for (int idx = tid; idx < 128 * D; idx += 256) {
        int n = idx >> 7, k = idx & 127;
        bool ok = (n0 + n < N_);
        Ht[k * 132 + n] = ok ? h[(size_t)(n0 + n) * D + k] : 0.0f;
        Mt[k * 132 + n] = ok ? m[(size_t)(n0 + n) * D + k] : 0.0f;
    }
    for (int idx = tid; idx < D * D; idx += 256) {
        int d = idx >> 7, k = idx & 127;
        Wt[k * D + d] = lw[(size_t)d * 256 + k];        // stage 1: h part
    }
    __syncthreads();

    u64 acc[4][8];
#pragma unroll
    for (int p = 0; p < 4; p++)
#pragma unroll
        for (int j = 0; j < 8; j++) acc[p][j] = 0ull;

#pragma unroll 2
    for (int k = 0; k < D; k++) {
        const float* Uk = Ht + k * 132 + e0t;
        u64 a[4];
#pragma unroll
        for (int p = 0; p < 4; p++) a[p] = *(const u64*)(Uk + 2 * p);
        const float* Wg = Wt + k * D + tx;
#pragma unroll
        for (int j = 0; j < 8; j++) {
            u64 wp = pack2same(Wg[16 * j]);
#pragma unroll
            for (int p = 0; p < 4; p++) fma2(acc[p][j], a[p], wp);
        }
    }
    __syncthreads();   // stage-1 reads of Wt done

    for (int idx = tid; idx < D * D; idx += 256) {
        int d = idx >> 7, k = idx & 127;
        Wt[k * D + d] = lw[(size_t)d * 256 + 128 + k];  // stage 2: m part
    }
    __syncthreads();

#pragma unroll 2
    for (int k = 0; k < D; k++) {
        const float* Uk = Mt + k * 132 + e0t;
        u64 a[4];
#pragma unroll
        for (int p = 0; p < 4; p++) a[p] = *(const u64*)(Uk + 2 * p);
        const float* Wg = Wt + k * D + tx;
#pragma unroll
        for (int j = 0; j < 8; j++) {
            u64 wp = pack2same(Wg[16 * j]);
#pragma unroll
            for (int p = 0; p < 4; p++) fma2(acc[p][j], a[p], wp);
        }
    }

#pragma unroll
    for (int j = 0; j < 8; j++) {
        int d = tx + 16 * j;
        float bb = lb[d];
#pragma unroll
        for (int p = 0; p < 4; p++) {
            float2 v = unpack2(acc[p][j]);
            int nl = e0t + 2 * p;
#pragma unroll
            for (int hh = 0; hh < 2; hh++) {
                int n1 = n0 + nl + hh;
                if (n1 < N_) {
                    float hv = Ht[d * 132 + nl + hh];   // original h[n][d]
                    float r = hv + (hh ? v.y : v.x) + bb;
                    h[(size_t)n1 * D + d] = r;
                    if (out2) out2[(size_t)n1 * D + d] = r;
                }
            }
        }
    }
}

// =======================================================================
extern "C" void kernel_launch(void* const* d_in, const int* in_sizes, int n_in,
                              void* d_out, int out_size)
{
    const float* z        = (const float*)d_in[0];
    const void*  eidx     = d_in[1];                 // int32 OR int64 — detected on device
    const float* elen     = (const float*)d_in[2];
    const float* eattr    = (const float*)d_in[3];
    const float* emblin_w = (const float*)d_in[4];
    const float* emblin_b = (const float*)d_in[5];
    const float* mlp_w1   = (const float*)d_in[6];
    const float* mlp_b1   = (const float*)d_in[7];
    const float* mlp_w2   = (const float*)d_in[8];
    const float* mlp_b2   = (const float*)d_in[9];
    const float* lin1_w   = (const float*)d_in[10];
    const float* lin2_w   = (const float*)d_in[11];
    const float* lin2_b   = (const float*)d_in[12];
    const float* lin_w    = (const float*)d_in[13];
    const float* lin_b    = (const float*)d_in[14];
    float* out = (float*)d_out;

    const int N_ = in_sizes[0] / (NIN + D);
    const int E_ = in_sizes[2];
    const int L_ = in_sizes[7] / D;   // mlp_b1 is (L, D)

    float *hp, *xfp, *mip, *mp;
    int *srcp, *dstp;
    cudaGetSymbolAddress((void**)&hp,  g_h);
    cudaGetSymbolAddress((void**)&xfp, g_xf);
    cudaGetSymbolAddress((void**)&mip, g_mi);
    cudaGetSymbolAddress((void**)&mp,  g_m);
    cudaGetSymbolAddress((void**)&srcp, g_src);
    cudaGetSymbolAddress((void**)&dstp, g_dst);

    const size_t smemE = (size_t)(D * G + D * D + BE * 132 + D + D + BE) * 4
                       + (size_t)(2 * BE) * 4;                 // 186,880 B
    const size_t smemA = (size_t)(D * D + 128 * 132) * 4;      // 133,120 B
    const size_t smemU = (size_t)(D * D + 2 * 128 * 132) * 4;  // 200,704 B

    cudaFuncSetAttribute(edge_kernel,      cudaFuncAttributeMaxDynamicSharedMemorySize, (int)smemE);
    cudaFuncSetAttribute(node_gemm_kernel, cudaFuncAttributeMaxDynamicSharedMemorySize, (int)smemA);
    cudaFuncSetAttribute(update_kernel,    cudaFuncAttributeMaxDynamicSharedMemorySize, (int)smemU);

    int nsm = 148;
    cudaDeviceGetAttribute(&nsm, cudaDevAttrMultiProcessorCount, 0);

    const int ntiles = (E_ + BE - 1) / BE;
    const int egrid  = (ntiles < nsm) ? ntiles : nsm;
    const int nb     = (N_ + 127) / 128;
    const int elemsN = N_ * D;

    // index dtype detection + conversion (once; indices constant across layers)
    detect_kernel<<<1, 256>>>((const int*)eidx);
    convert_idx_kernel<<<(E_ + 255) / 256, 256>>>(eidx, E_, N_);

    embed_kernel<<<(elemsN + 255) / 256, 256>>>(z, emblin_w, emblin_b, hp, N_);

    for (int l = 0; l < L_; l++) {
        const float* w1 = mlp_w1 + (size_t)l * D * G;
        const float* b1 = mlp_b1 + (size_t)l * D;
        const float* w2 = mlp_w2 + (size_t)l * D * D;
        const float* b2 = mlp_b2 + (size_t)l * D;
        const float* l1w = lin1_w + (size_t)l * D * D;
        const float* l2w = lin2_w + (size_t)l * D * D;
        const float* l2b = lin2_b + (size_t)l * D;
        const float* lw  = lin_w  + (size_t)l * D * 2 * D;
        const float* lb  = lin_b  + (size_t)l * D;

        zero_kernel<<<(elemsN + 255) / 256, 256>>>(mip, elemsN);
        node_gemm_kernel<<<nb, 256, smemA>>>(hp, l1w, nullptr, xfp, N_, 0);
        edge_kernel<<<egrid, 256, smemE>>>(eattr, srcp, dstp, elen, w1, b1, w2, b2,
                                           xfp, mip, E_);
        node_gemm_kernel<<<nb, 256, smemA>>>(mip, l2w, l2b, mp, N_, 1);
        update_kernel<<<nb, 256, smemU>>>(hp, mp, lw, lb, N_,
                                          (l == L_ - 1) ? out : nullptr);
    }
}

// round 11
// speedup vs baseline: 1.1332x; 1.1332x over previous
#include <cuda_runtime.h>
#include <cstdint>
#include <cstddef>

#define D 128
#define G 100
#define NIN 5          // INPUT_DIM
#define BE 128         // edges per tile
#define NMAX 20000
#define EMAX 320000
#define LOG2F_ 0.6931471805599453f

// ---------------- device scratch (no allocation allowed) ----------------
__device__ __align__(256) float g_h [NMAX * D];
__device__ __align__(256) float g_xf[NMAX * D];
__device__ __align__(256) float g_mi[NMAX * D];
__device__ __align__(256) float g_m [NMAX * D];
__device__ __align__(256) int   g_src[EMAX];
__device__ __align__(256) int   g_dst[EMAX];

typedef unsigned long long u64;

// packed fp32x2 FMA (sm_100+): c = a*b + c on both lanes
__device__ __forceinline__ void fma2(u64 &c, u64 a, u64 b) {
    asm("fma.rn.f32x2 %0, %1, %2, %0;" : "+l"(c) : "l"(a), "l"(b));
}
__device__ __forceinline__ u64 pack2same(float w) {
    u64 r; asm("mov.b64 %0, {%1, %1};" : "=l"(r) : "f"(w)); return r;
}
__device__ __forceinline__ float2 unpack2(u64 v) {
    float2 r; asm("mov.b64 {%0, %1}, %2;" : "=f"(r.x), "=f"(r.y) : "l"(v)); return r;
}
// shifted softplus: log(1+e^x) - log(2); fast path: arg of __logf in (1,2]
__device__ __forceinline__ float sspf(float x) {
    return fmaxf(x, 0.0f) + __logf(1.0f + __expf(-fabsf(x))) - LOG2F_;
}

// =======================================================================
// Index conversion with inline dtype detection.
// Values are in [0, N) << 2^31. If buffer is int64 (LE), every odd 32-bit
// word (high half) of the first 1024 entries is 0; if int32, those words
// are random indices (never all zero). Each block re-derives the flag
// (4 KB of L2-hit reads; kernel runs once per launch).
// =======================================================================
__global__ void convert_idx_kernel(const void* __restrict__ ei, int E_, int N_)
{
    __shared__ int s_or;
    if (threadIdx.x == 0) s_or = 0;
    __syncthreads();
    {
        const int* w = (const int*)ei;
        int v = 0;
        for (int i = threadIdx.x; i < 1024; i += blockDim.x) v |= w[2 * i + 1];
        if (v) atomicOr(&s_or, 1);
    }
    __syncthreads();
    const bool is64 = (s_or == 0);

    int e = blockIdx.x * blockDim.x + threadIdx.x;
    if (e >= E_) return;
    long long s, d;
    if (is64) {
        const long long* p = (const long long*)ei;
        s = p[e]; d = p[E_ + e];
    } else {
        const int* p = (const int*)ei;
        s = p[e]; d = p[E_ + e];
    }
    g_src[e] = (s >= 0 && s < N_) ? (int)s : 0;
    g_dst[e] = (d >= 0 && d < N_) ? (int)d : 0;
}

// =======================================================================
// Embedding: h = zf @ emblin_w.T + emblin_b + ptemb
// =======================================================================
__global__ void embed_kernel(const float* __restrict__ z,
                             const float* __restrict__ ew,
                             const float* __restrict__ eb,
                             float* __restrict__ h, int N_)
{
    int i = blockIdx.x * blockDim.x + threadIdx.x;
    if (i >= N_ * D) return;
    int n = i >> 7, d = i & 127;
    const float* zr = z + (size_t)n * (NIN + D);
    float acc = eb[d] + zr[NIN + d];
#pragma unroll
    for (int k = 0; k < NIN; k++) acc = fmaf(zr[k], ew[d * NIN + k], acc);
    h[i] = acc;
}

// =======================================================================
// Edge kernel (persistent): per 128-edge tile:
//   T  = ssp(EA @ W1.T + b1)            (K = 100)
//   Wf = (T @ W2.T + b2) * C            (K = 128)
//   m_i[dst] += xf[src] * Wf            (float4 atomics)
// Thread tile: 8 edges x 8 outputs, packed f32x2 over edge pairs.
// =======================================================================
__global__ __launch_bounds__(256, 1)
void edge_kernel(const float* __restrict__ edge_attr,
                 const int* __restrict__ esrc,
                 const int* __restrict__ edst,
                 const float* __restrict__ edge_length,
                 const float* __restrict__ w1, const float* __restrict__ b1,
                 const float* __restrict__ w2, const float* __restrict__ b2,
                 const float* __restrict__ xf, float* __restrict__ mi,
                 int E_)
{
    extern __shared__ float sm[];
    float* W1t = sm;                 // [100][128]           12800 f
    float* W2t = W1t + G * D;        // [128][128]           16384 f
    float* U   = W2t + D * D;        // union, 128 x 132     16896 f
    float* B1  = U + BE * 132;       // 128 f
    float* B2  = B1 + D;             // 128 f
    float* CeS = B2 + D;             // 128 f
    int*   srcS = (int*)(CeS + BE);  // 128 i
    int*   dstS = srcS + BE;         // 128 i

    const int tid = threadIdx.x;
    const int tx  = tid & 15;        // output-d group: d = tx + 16*j
    const int ty  = tid >> 4;        // edge group of 8: e = 8*ty + {0..7}
    const int e0t = ty * 8;

    // load weights transposed (once per block)
    for (int idx = tid; idx < D * G; idx += 256) {
        int d = idx / G, g = idx - d * G;
        W1t[g * D + d] = w1[idx];
    }
    for (int idx = tid; idx < D * D; idx += 256) {
        int d = idx >> 7, k = idx & 127;
        W2t[k * D + d] = w2[idx];
    }
    if (tid < D) { B1[tid] = b1[tid]; B2[tid] = b2[tid]; }
    __syncthreads();

    const int ntiles = (E_ + BE - 1) / BE;
    for (int t = blockIdx.x; t < ntiles; t += gridDim.x) {
        const int ebase = t * BE;

        // edge metadata
        if (tid < BE) {
            int e = ebase + tid;
            if (e < E_) {
                srcS[tid] = esrc[e];
                dstS[tid] = edst[e];
                CeS[tid]  = (edge_length[e] <= 10.0f) ? 1.0f : 0.0f;
            } else {
                srcS[tid] = 0; dstS[tid] = 0; CeS[tid] = 0.0f;
            }
        }
        // EA tile transposed into U: U[g*128 + e]
        for (int idx = tid; idx < BE * G; idx += 256) {
            int e = idx / G, g = idx - e * G;
            int ge = ebase + e;
            U[g * BE + e] = (ge < E_) ? edge_attr[(size_t)ge * G + g] : 0.0f;
        }
        __syncthreads();

        // ---- GEMM1: K = 100 ----
        u64 acc[4][8];
#pragma unroll
        for (int p = 0; p < 4; p++)
#pragma unroll
            for (int j = 0; j < 8; j++) acc[p][j] = 0ull;

#pragma unroll 4
        for (int g = 0; g < G; g++) {
            const float* Ug = U + g * BE + e0t;
            u64 a[4];
#pragma unroll
            for (int p = 0; p < 4; p++) a[p] = *(const u64*)(Ug + 2 * p);
            const float* Wg = W1t + g * D + tx;
#pragma unroll
            for (int j = 0; j < 8; j++) {
                u64 wp = pack2same(Wg[16 * j]);
#pragma unroll
                for (int p = 0; p < 4; p++) fma2(acc[p][j], a[p], wp);
            }
        }
        __syncthreads();   // all reads of EA tile done

        // ssp + store T into U with row stride 132 (rows = k index)
#pragma unroll
        for (int j = 0; j < 8; j++) {
            int k = tx + 16 * j;
            float bb = B1[k];
            float* Ur = U + k * 132 + e0t;
#pragma unroll
            for (int p = 0; p < 4; p++) {
                float2 v = unpack2(acc[p][j]);
                Ur[2 * p]     = sspf(v.x + bb);
                Ur[2 * p + 1] = sspf(v.y + bb);
            }
        }
        __syncthreads();

        // ---- GEMM2: K = 128 ----
#pragma unroll
        for (int p = 0; p < 4; p++)
#pragma unroll
            for (int j = 0; j < 8; j++) acc[p][j] = 0ull;

#pragma unroll 4
        for (int k = 0; k < D; k++) {
            const float* Uk = U + k * 132 + e0t;
            u64 a[4];
#pragma unroll
            for (int p = 0; p < 4; p++) a[p] = *(const u64*)(Uk + 2 * p);
            const float* Wg = W2t + k * D + tx;
#pragma unroll
            for (int j = 0; j < 8; j++) {
                u64 wp = pack2same(Wg[16 * j]);
#pragma unroll
                for (int p = 0; p < 4; p++) fma2(acc[p][j], a[p], wp);
            }
        }
        __syncthreads();   // all reads of T done

        // Wf*C into U, now per-edge rows: U[e*132 + d]
#pragma unroll
        for (int j = 0; j < 8; j++) {
            int d = tx + 16 * j;
            float bb = B2[d];
#pragma unroll
            for (int p = 0; p < 4; p++) {
                float2 v = unpack2(acc[p][j]);
                int ea = e0t + 2 * p;
                U[ea * 132 + d]       = (v.x + bb) * CeS[ea];
                U[(ea + 1) * 132 + d] = (v.y + bb) * CeS[ea + 1];
            }
        }
        __syncthreads();

        // scatter: m_i[dst] += xf[src] * Wf   (float4 vector atomics)
        for (int idx = tid; idx < BE * (D / 4); idx += 256) {
            int e = idx >> 5;          // D/4 == 32
            int q = idx & 31;
            if (ebase + e < E_) {
                float4 wf = *(const float4*)(U + e * 132 + q * 4);
                int s = srcS[e], dd = dstS[e];
                float4 x4 = *(const float4*)(xf + (size_t)s * D + q * 4);
                float4 v;
                v.x = wf.x * x4.x; v.y = wf.y * x4.y;
                v.z = wf.z * x4.z; v.w = wf.w * x4.w;
                atomicAdd((float4*)(mi + (size_t)dd * D) + q, v);
            }
        }
        __syncthreads();
    }
}

// =======================================================================
// Node GEMM: out = act(in @ w.T [+ bias]); mode 0: plain, 1: bias+ssp
// Tile: 128 rows x 128 cols per block. If zbuf != null, also zero the
// corresponding tile of zbuf (fused mi-clear for the xf pass).
// =======================================================================
__global__ __launch_bounds__(256, 1)
void node_gemm_kernel(const float* __restrict__ in,
                      const float* __restrict__ w,     // [128][128] (out,in)
                      const float* __restrict__ bias,  // may be null
                      float* __restrict__ out,
                      int N_, int mode,
                      float* __restrict__ zbuf)
{
    extern __shared__ float sm[];
    float* Wt = sm;            // 16384 f
    float* Ht = Wt + D * D;    // 128 x 132

    const int tid = threadIdx.x;
    const int tx = tid & 15, ty = tid >> 4;
    const int e0t = ty * 8;
    const int n0 = blockIdx.x * 128;

    if (zbuf) {
        float4 z4 = make_float4(0.f, 0.f, 0.f, 0.f);
        for (int idx = tid; idx < 128 * (D / 4); idx += 256) {
            int n = n0 + (idx >> 5);
            if (n < N_) ((float4*)(zbuf + (size_t)n * D))[idx & 31] = z4;
        }
    }

    for (int idx = tid; idx < D * D; idx += 256) {
        int d = idx >> 7, k = idx & 127;
        Wt[k * D + d] = w[idx];
    }
    for (int idx = tid; idx < 128 * D; idx += 256) {
        int n = idx >> 7, k = idx & 127;
        Ht[k * 132 + n] = (n0 + n < N_) ? in[(size_t)(n0 + n) * D + k] : 0.0f;
    }
    __syncthreads();

    u64 acc[4][8];
#pragma unroll
    for (int p = 0; p < 4; p++)
#pragma unroll
        for (int j = 0; j < 8; j++) acc[p][j] = 0ull;

#pragma unroll 4
    for (int k = 0; k < D; k++) {
        const float* Uk = Ht + k * 132 + e0t;
        u64 a[4];
#pragma unroll
        for (int p = 0; p < 4; p++) a[p] = *(const u64*)(Uk + 2 * p);
        const float* Wg = Wt + k * D + tx;
#pragma unroll
        for (int j = 0; j < 8; j++) {
            u64 wp = pack2same(Wg[16 * j]);
#pragma unroll
            for (int p = 0; p < 4; p++) fma2(acc[p][j], a[p], wp);
        }
    }

#pragma unroll
    for (int j = 0; j < 8; j++) {
        int d = tx + 16 * j;
        float bb = bias ? bias[d] : 0.0f;
#pragma unroll
        for (int p = 0; p < 4; p++) {
            float2 v = unpack2(acc[p][j]);
            int n1 = n0 + e0t + 2 * p;
            if (n1 < N_) {
                float r = v.x + bb;
                out[(size_t)n1 * D + d] = mode ? sspf(r) : r;
            }
            if (n1 + 1 < N_) {
                float r = v.y + bb;
                out[(size_t)(n1 + 1) * D + d] = mode ? sspf(r) : r;
            }
        }
    }
}

// =======================================================================
// Update: h = h + concat([h, m]) @ lin_w.T + lin_b
//       = h + h @ lwA.T + m @ lwB.T + b   (two weight stages, one buffer)
// Optionally also writes out2 (final layer -> d_out).
// =======================================================================
__global__ __launch_bounds__(256, 1)
void update_kernel(float* __restrict__ h, const float* __restrict__ m,
                   const float* __restrict__ lw,   // [128][256]
                   const float* __restrict__ lb,
                   int N_, float* __restrict__ out2)
{
    extern __shared__ float sm[];
    float* Wt = sm;                  // 16384 f (reloaded per stage)
    float* Ht = Wt + D * D;          // 128 x 132
    float* Mt = Ht + 128 * 132;      // 128 x 132

    const int tid = threadIdx.x;
    const int tx = tid & 15, ty = tid >> 4;
    const int e0t = ty * 8;
    const int n0 = blockIdx.x * 128;

    for (int idx = tid; idx < 128 * D; idx += 256) {
        int n = idx >> 7, k = idx & 127;
        bool ok = (n0 + n < N_);
        Ht[k * 132 + n] = ok ? h[(size_t)(n0 + n) * D + k] : 0.0f;
        Mt[k * 132 + n] = ok ? m[(size_t)(n0 + n) * D + k] : 0.0f;
    }
    for (int idx = tid; idx < D * D; idx += 256) {
        int d = idx >> 7, k = idx & 127;
        Wt[k * D + d] = lw[(size_t)d * 256 + k];        // stage 1: h part
    }
    __syncthreads();

    u64 acc[4][8];
#pragma unroll
    for (int p = 0; p < 4; p++)
#pragma unroll
        for (int j = 0; j < 8; j++) acc[p][j] = 0ull;

#pragma unroll 4
    for (int k = 0; k < D; k++) {
        const float* Uk = Ht + k * 132 + e0t;
        u64 a[4];
#pragma unroll
        for (int p = 0; p < 4; p++) a[p] = *(const u64*)(Uk + 2 * p);
        const float* Wg = Wt + k * D + tx;
#pragma unroll
        for (int j = 0; j < 8; j++) {
            u64 wp = pack2same(Wg[16 * j]);
#pragma unroll
            for (int p = 0; p < 4; p++) fma2(acc[p][j], a[p], wp);
        }
    }
    __syncthreads();   // stage-1 reads of Wt done

    for (int idx = tid; idx < D * D; idx += 256) {
        int d = idx >> 7, k = idx & 127;
        Wt[k * D + d] = lw[(size_t)d * 256 + 128 + k];  // stage 2: m part
    }
    __syncthreads();

#pragma unroll 4
    for (int k = 0; k < D; k++) {
        const float* Uk = Mt + k * 132 + e0t;
        u64 a[4];
#pragma unroll
        for (int p = 0; p < 4; p++) a[p] = *(const u64*)(Uk + 2 * p);
        const float* Wg = Wt + k * D + tx;
#pragma unroll
        for (int j = 0; j < 8; j++) {
            u64 wp = pack2same(Wg[16 * j]);
#pragma unroll
            for (int p = 0; p < 4; p++) fma2(acc[p][j], a[p], wp);
        }
    }

#pragma unroll
    for (int j = 0; j < 8; j++) {
        int d = tx + 16 * j;
        float bb = lb[d];
#pragma unroll
        for (int p = 0; p < 4; p++) {
            float2 v = unpack2(acc[p][j]);
            int nl = e0t + 2 * p;
#pragma unroll
            for (int hh = 0; hh < 2; hh++) {
                int n1 = n0 + nl + hh;
                if (n1 < N_) {
                    float hv = Ht[d * 132 + nl + hh];   // original h[n][d]
                    float r = hv + (hh ? v.y : v.x) + bb;
                    h[(size_t)n1 * D + d] = r;
                    if (out2) out2[(size_t)n1 * D + d] = r;
                }
            }
        }
    }
}

// =======================================================================
extern "C" void kernel_launch(void* const* d_in, const int* in_sizes, int n_in,
                              void* d_out, int out_size)
{
    const float* z        = (const float*)d_in[0];
    const void*  eidx     = d_in[1];                 // int32 OR int64 — detected on device
    const float* elen     = (const float*)d_in[2];
    const float* eattr    = (const float*)d_in[3];
    const float* emblin_w = (const float*)d_in[4];
    const float* emblin_b = (const float*)d_in[5];
    const float* mlp_w1   = (const float*)d_in[6];
    const float* mlp_b1   = (const float*)d_in[7];
    const float* mlp_w2   = (const float*)d_in[8];
    const float* mlp_b2   = (const float*)d_in[9];
    const float* lin1_w   = (const float*)d_in[10];
    const float* lin2_w   = (const float*)d_in[11];
    const float* lin2_b   = (const float*)d_in[12];
    const float* lin_w    = (const float*)d_in[13];
    const float* lin_b    = (const float*)d_in[14];
    float* out = (float*)d_out;

    const int N_ = in_sizes[0] / (NIN + D);
    const int E_ = in_sizes[2];
    const int L_ = in_sizes[7] / D;   // mlp_b1 is (L, D)

    float *hp, *xfp, *mip, *mp;
    int *srcp, *dstp;
    cudaGetSymbolAddress((void**)&hp,  g_h);
    cudaGetSymbolAddress((void**)&xfp, g_xf);
    cudaGetSymbolAddress((void**)&mip, g_mi);
    cudaGetSymbolAddress((void**)&mp,  g_m);
    cudaGetSymbolAddress((void**)&srcp, g_src);
    cudaGetSymbolAddress((void**)&dstp, g_dst);

    const size_t smemE = (size_t)(D * G + D * D + BE * 132 + D + D + BE) * 4
                       + (size_t)(2 * BE) * 4;                 // 186,880 B
    const size_t smemA = (size_t)(D * D + 128 * 132) * 4;      // 133,120 B
    const size_t smemU = (size_t)(D * D + 2 * 128 * 132) * 4;  // 200,704 B

    cudaFuncSetAttribute(edge_kernel,      cudaFuncAttributeMaxDynamicSharedMemorySize, (int)smemE);
    cudaFuncSetAttribute(node_gemm_kernel, cudaFuncAttributeMaxDynamicSharedMemorySize, (int)smemA);
    cudaFuncSetAttribute(update_kernel,    cudaFuncAttributeMaxDynamicSharedMemorySize, (int)smemU);

    int nsm = 148;
    cudaDeviceGetAttribute(&nsm, cudaDevAttrMultiProcessorCount, 0);

    const int ntiles = (E_ + BE - 1) / BE;
    const int egrid  = (ntiles < nsm) ? ntiles : nsm;
    const int nb     = (N_ + 127) / 128;
    const int elemsN = N_ * D;

    // index conversion with inline dtype detection (once; layer-invariant)
    convert_idx_kernel<<<(E_ + 255) / 256, 256>>>(eidx, E_, N_);

    embed_kernel<<<(elemsN + 255) / 256, 256>>>(z, emblin_w, emblin_b, hp, N_);

    for (int l = 0; l < L_; l++) {
        const float* w1 = mlp_w1 + (size_t)l * D * G;
        const float* b1 = mlp_b1 + (size_t)l * D;
        const float* w2 = mlp_w2 + (size_t)l * D * D;
        const float* b2 = mlp_b2 + (size_t)l * D;
        const float* l1w = lin1_w + (size_t)l * D * D;
        const float* l2w = lin2_w + (size_t)l * D * D;
        const float* l2b = lin2_b + (size_t)l * D;
        const float* lw  = lin_w  + (size_t)l * D * 2 * D;
        const float* lb  = lin_b  + (size_t)l * D;

        // xf = h @ lin1.T, fused with zeroing of mi
        node_gemm_kernel<<<nb, 256, smemA>>>(hp, l1w, nullptr, xfp, N_, 0, mip);
        edge_kernel<<<egrid, 256, smemE>>>(eattr, srcp, dstp, elen, w1, b1, w2, b2,
                                           xfp, mip, E_);
        node_gemm_kernel<<<nb, 256, smemA>>>(mip, l2w, l2b, mp, N_, 1, nullptr);
        update_kernel<<<nb, 256, smemU>>>(hp, mp, lw, lb, N_,
                                          (l == L_ - 1) ? out : nullptr);
    }
}

// round 12
// speedup vs baseline: 1.3056x; 1.1521x over previous
#include <cuda_runtime.h>
#include <cstdint>
#include <cstddef>

#define D 128
#define G 100
#define NIN 5          // INPUT_DIM
#define BE 128         // edges per tile
#define NMAX 20000
#define EMAX 320000
#define NT 512         // threads per block (GEMM kernels)
#define LOG2F_ 0.6931471805599453f

// ---------------- device scratch (no allocation allowed) ----------------
__device__ __align__(256) float g_h [NMAX * D];
__device__ __align__(256) float g_xf[NMAX * D];
__device__ __align__(256) float g_mi[NMAX * D];
__device__ __align__(256) float g_m [NMAX * D];
__device__ __align__(256) int   g_src[EMAX];
__device__ __align__(256) int   g_dst[EMAX];

typedef unsigned long long u64;

// packed fp32x2 FMA (sm_100+): c = a*b + c on both lanes
__device__ __forceinline__ void fma2(u64 &c, u64 a, u64 b) {
    asm("fma.rn.f32x2 %0, %1, %2, %0;" : "+l"(c) : "l"(a), "l"(b));
}
__device__ __forceinline__ u64 pack2same(float w) {
    u64 r; asm("mov.b64 %0, {%1, %1};" : "=l"(r) : "f"(w)); return r;
}
__device__ __forceinline__ float2 unpack2(u64 v) {
    float2 r; asm("mov.b64 {%0, %1}, %2;" : "=f"(r.x), "=f"(r.y) : "l"(v)); return r;
}
// shifted softplus: log(1+e^x) - log(2); fast path: arg of __logf in (1,2]
__device__ __forceinline__ float sspf(float x) {
    return fmaxf(x, 0.0f) + __logf(1.0f + __expf(-fabsf(x))) - LOG2F_;
}

// =======================================================================
// Index conversion with inline dtype detection (see R7 notes).
// =======================================================================
__global__ void convert_idx_kernel(const void* __restrict__ ei, int E_, int N_)
{
    __shared__ int s_or;
    if (threadIdx.x == 0) s_or = 0;
    __syncthreads();
    {
        const int* w = (const int*)ei;
        int v = 0;
        for (int i = threadIdx.x; i < 1024; i += blockDim.x) v |= w[2 * i + 1];
        if (v) atomicOr(&s_or, 1);
    }
    __syncthreads();
    const bool is64 = (s_or == 0);

    int e = blockIdx.x * blockDim.x + threadIdx.x;
    if (e >= E_) return;
    long long s, d;
    if (is64) {
        const long long* p = (const long long*)ei;
        s = p[e]; d = p[E_ + e];
    } else {
        const int* p = (const int*)ei;
        s = p[e]; d = p[E_ + e];
    }
    g_src[e] = (s >= 0 && s < N_) ? (int)s : 0;
    g_dst[e] = (d >= 0 && d < N_) ? (int)d : 0;
}

// =======================================================================
// Embedding: h = zf @ emblin_w.T + emblin_b + ptemb
// =======================================================================
__global__ void embed_kernel(const float* __restrict__ z,
                             const float* __restrict__ ew,
                             const float* __restrict__ eb,
                             float* __restrict__ h, int N_)
{
    int i = blockIdx.x * blockDim.x + threadIdx.x;
    if (i >= N_ * D) return;
    int n = i >> 7, d = i & 127;
    const float* zr = z + (size_t)n * (NIN + D);
    float acc = eb[d] + zr[NIN + d];
#pragma unroll
    for (int k = 0; k < NIN; k++) acc = fmaf(zr[k], ew[d * NIN + k], acc);
    h[i] = acc;
}

// =======================================================================
// Edge kernel (persistent, 512 thr): per 128-edge tile:
//   T  = ssp(EA @ W1.T + b1)            (K = 100)
//   Wf = (T @ W2.T + b2) * C            (K = 128)
//   m_i[dst] += xf[src] * Wf            (float4 atomics)
// Thread tile: 8 edges x 4 outputs. 16 warps/SM -> 4/SMSP (latency fix).
// =======================================================================
__global__ __launch_bounds__(NT, 1)
void edge_kernel(const float* __restrict__ edge_attr,
                 const int* __restrict__ esrc,
                 const int* __restrict__ edst,
                 const float* __restrict__ edge_length,
                 const float* __restrict__ w1, const float* __restrict__ b1,
                 const float* __restrict__ w2, const float* __restrict__ b2,
                 const float* __restrict__ xf, float* __restrict__ mi,
                 int E_)
{
    extern __shared__ float sm[];
    float* W1t = sm;                 // [100][128]           12800 f
    float* W2t = W1t + G * D;        // [128][128]           16384 f
    float* U   = W2t + D * D;        // union, 128 x 132     16896 f
    float* B1  = U + BE * 132;       // 128 f
    float* B2  = B1 + D;             // 128 f
    float* CeS = B2 + D;             // 128 f
    int*   srcS = (int*)(CeS + BE);  // 128 i
    int*   dstS = srcS + BE;         // 128 i

    const int tid = threadIdx.x;
    const int tx  = tid & 31;        // output-d group: d = tx + 32*j, j<4
    const int ty  = tid >> 5;        // edge group of 8 (== warp id)
    const int e0t = ty * 8;

    // load weights transposed (once per block)
    for (int idx = tid; idx < D * G; idx += NT) {
        int d = idx / G, g = idx - d * G;
        W1t[g * D + d] = w1[idx];
    }
    for (int idx = tid; idx < D * D; idx += NT) {
        int d = idx >> 7, k = idx & 127;
        W2t[k * D + d] = w2[idx];
    }
    if (tid < D) { B1[tid] = b1[tid]; B2[tid] = b2[tid]; }
    __syncthreads();

    const int ntiles = (E_ + BE - 1) / BE;
    for (int t = blockIdx.x; t < ntiles; t += gridDim.x) {
        const int ebase = t * BE;

        // edge metadata
        if (tid < BE) {
            int e = ebase + tid;
            if (e < E_) {
                srcS[tid] = esrc[e];
                dstS[tid] = edst[e];
                CeS[tid]  = (edge_length[e] <= 10.0f) ? 1.0f : 0.0f;
            } else {
                srcS[tid] = 0; dstS[tid] = 0; CeS[tid] = 0.0f;
            }
        }
        // EA tile transposed into U: U[g*128 + e]
        for (int idx = tid; idx < BE * G; idx += NT) {
            int e = idx / G, g = idx - e * G;
            int ge = ebase + e;
            U[g * BE + e] = (ge < E_) ? edge_attr[(size_t)ge * G + g] : 0.0f;
        }
        __syncthreads();

        // ---- GEMM1: K = 100 ----
        u64 acc[4][4];
#pragma unroll
        for (int p = 0; p < 4; p++)
#pragma unroll
            for (int j = 0; j < 4; j++) acc[p][j] = 0ull;

#pragma unroll 4
        for (int g = 0; g < G; g++) {
            const float* Ug = U + g * BE + e0t;
            u64 a[4];
#pragma unroll
            for (int p = 0; p < 4; p++) a[p] = *(const u64*)(Ug + 2 * p);
            const float* Wg = W1t + g * D + tx;
#pragma unroll
            for (int j = 0; j < 4; j++) {
                u64 wp = pack2same(Wg[32 * j]);
#pragma unroll
                for (int p = 0; p < 4; p++) fma2(acc[p][j], a[p], wp);
            }
        }
        __syncthreads();   // all reads of EA tile done

        // ssp + store T into U with row stride 132 (rows = k index)
#pragma unroll
        for (int j = 0; j < 4; j++) {
            int k = tx + 32 * j;
            float bb = B1[k];
            float* Ur = U + k * 132 + e0t;
#pragma unroll
            for (int p = 0; p < 4; p++) {
                float2 v = unpack2(acc[p][j]);
                Ur[2 * p]     = sspf(v.x + bb);
                Ur[2 * p + 1] = sspf(v.y + bb);
            }
        }
        __syncthreads();

        // ---- GEMM2: K = 128 ----
#pragma unroll
        for (int p = 0; p < 4; p++)
#pragma unroll
            for (int j = 0; j < 4; j++) acc[p][j] = 0ull;

#pragma unroll 4
        for (int k = 0; k < D; k++) {
            const float* Uk = U + k * 132 + e0t;
            u64 a[4];
#pragma unroll
            for (int p = 0; p < 4; p++) a[p] = *(const u64*)(Uk + 2 * p);
            const float* Wg = W2t + k * D + tx;
#pragma unroll
            for (int j = 0; j < 4; j++) {
                u64 wp = pack2same(Wg[32 * j]);
#pragma unroll
                for (int p = 0; p < 4; p++) fma2(acc[p][j], a[p], wp);
            }
        }
        __syncthreads();   // all reads of T done

        // Wf*C into U, now per-edge rows: U[e*132 + d]
#pragma unroll
        for (int j = 0; j < 4; j++) {
            int d = tx + 32 * j;
            float bb = B2[d];
#pragma unroll
            for (int p = 0; p < 4; p++) {
                float2 v = unpack2(acc[p][j]);
                int ea = e0t + 2 * p;
                U[ea * 132 + d]       = (v.x + bb) * CeS[ea];
                U[(ea + 1) * 132 + d] = (v.y + bb) * CeS[ea + 1];
            }
        }
        __syncthreads();

        // scatter: m_i[dst] += xf[src] * Wf   (float4 vector atomics)
        for (int idx = tid; idx < BE * (D / 4); idx += NT) {
            int e = idx >> 5;          // D/4 == 32
            int q = idx & 31;
            if (ebase + e < E_) {
                float4 wf = *(const float4*)(U + e * 132 + q * 4);
                int s = srcS[e], dd = dstS[e];
                float4 x4 = *(const float4*)(xf + (size_t)s * D + q * 4);
                float4 v;
                v.x = wf.x * x4.x; v.y = wf.y * x4.y;
                v.z = wf.z * x4.z; v.w = wf.w * x4.w;
                atomicAdd((float4*)(mi + (size_t)dd * D) + q, v);
            }
        }
        __syncthreads();
    }
}

// =======================================================================
// Node GEMM (512 thr): out = act(in @ w.T [+ bias]); mode 1: bias+ssp.
// Tile 128x128; thread tile 8 rows x 4 cols. Optional fused zbuf clear.
// =======================================================================
__global__ __launch_bounds__(NT, 1)
void node_gemm_kernel(const float* __restrict__ in,
                      const float* __restrict__ w,     // [128][128] (out,in)
                      const float* __restrict__ bias,  // may be null
                      float* __restrict__ out,
                      int N_, int mode,
                      float* __restrict__ zbuf)
{
    extern __shared__ float sm[];
    float* Wt = sm;            // 16384 f
    float* Ht = Wt + D * D;    // 128 x 132

    const int tid = threadIdx.x;
    const int tx = tid & 31, ty = tid >> 5;
    const int e0t = ty * 8;
    const int n0 = blockIdx.x * 128;

    if (zbuf) {
        float4 z4 = make_float4(0.f, 0.f, 0.f, 0.f);
        for (int idx = tid; idx < 128 * (D / 4); idx += NT) {
            int n = n0 + (idx >> 5);
            if (n < N_) ((float4*)(zbuf + (size_t)n * D))[idx & 31] = z4;
        }
    }

    for (int idx = tid; idx < D * D; idx += NT) {
        int d = idx >> 7, k = idx & 127;
        Wt[k * D + d] = w[idx];
    }
    for (int idx = tid; idx < 128 * D; idx += NT) {
        int n = idx >> 7, k = idx & 127;
        Ht[k * 132 + n] = (n0 + n < N_) ? in[(size_t)(n0 + n) * D + k] : 0.0f;
    }
    __syncthreads();

    u64 acc[4][4];
#pragma unroll
    for (int p = 0; p < 4; p++)
#pragma unroll
        for (int j = 0; j < 4; j++) acc[p][j] = 0ull;

#pragma unroll 4
    for (int k = 0; k < D; k++) {
        const float* Uk = Ht + k * 132 + e0t;
        u64 a[4];
#pragma unroll
        for (int p = 0; p < 4; p++) a[p] = *(const u64*)(Uk + 2 * p);
        const float* Wg = Wt + k * D + tx;
#pragma unroll
        for (int j = 0; j < 4; j++) {
            u64 wp = pack2same(Wg[32 * j]);
#pragma unroll
            for (int p = 0; p < 4; p++) fma2(acc[p][j], a[p], wp);
        }
    }

#pragma unroll
    for (int j = 0; j < 4; j++) {
        int d = tx + 32 * j;
        float bb = bias ? bias[d] : 0.0f;
#pragma unroll
        for (int p = 0; p < 4; p++) {
            float2 v = unpack2(acc[p][j]);
            int n1 = n0 + e0t + 2 * p;
            if (n1 < N_) {
                float r = v.x + bb;
                out[(size_t)n1 * D + d] = mode ? sspf(r) : r;
            }
            if (n1 + 1 < N_) {
                float r = v.y + bb;
                out[(size_t)(n1 + 1) * D + d] = mode ? sspf(r) : r;
            }
        }
    }
}

// =======================================================================
// Update (512 thr): h = h + concat([h, m]) @ lin_w.T + lin_b
// Two weight stages sharing one buffer; optional final-layer out2 write.
// =======================================================================
__global__ __launch_bounds__(NT, 1)
void update_kernel(float* __restrict__ h, const float* __restrict__ m,
                   const float* __restrict__ lw,   // [128][256]
                   const float* __restrict__ lb,
                   int N_, float* __restrict__ out2)
{
    extern __shared__ float sm[];
    float* Wt = sm;                  // 16384 f (reloaded per stage)
    float* Ht = Wt + D * D;          // 128 x 132
    float* Mt = Ht + 128 * 132;      // 128 x 132

    const int tid = threadIdx.x;
    const int tx = tid & 31, ty = tid >> 5;
    const int e0t = ty * 8;
    const int n0 = blockIdx.x * 128;

    for (int idx = tid; idx < 128 * D; idx += NT) {
        int n = idx >> 7, k = idx & 127;
        bool ok = (n0 + n < N_);
        Ht[k * 132 + n] = ok ? h[(size_t)(n0 + n) * D + k] : 0.0f;
        Mt[k * 132 + n] = ok ? m[(size_t)(n0 + n) * D + k] : 0.0f;
    }
    for (int idx = tid; idx < D * D; idx += NT) {
        int d = idx >> 7, k = idx & 127;
        Wt[k * D + d] = lw[(size_t)d * 256 + k];        // stage 1: h part
    }
    __syncthreads();

    u64 acc[4][4];
#pragma unroll
    for (int p = 0; p < 4; p++)
#pragma unroll
        for (int j = 0; j < 4; j++) acc[p][j] = 0ull;

#pragma unroll 4
    for (int k = 0; k < D; k++) {
        const float* Uk = Ht + k * 132 + e0t;
        u64 a[4];
#pragma unroll
        for (int p = 0; p < 4; p++) a[p] = *(const u64*)(Uk + 2 * p);
        const float* Wg = Wt + k * D + tx;
#pragma unroll
        for (int j = 0; j < 4; j++) {
            u64 wp = pack2same(Wg[32 * j]);
#pragma unroll
            for (int p = 0; p < 4; p++) fma2(acc[p][j], a[p], wp);
        }
    }
    __syncthreads();   // stage-1 reads of Wt done

    for (int idx = tid; idx < D * D; idx += NT) {
        int d = idx >> 7, k = idx & 127;
        Wt[k * D + d] = lw[(size_t)d * 256 + 128 + k];  // stage 2: m part
    }
    __syncthreads();

#pragma unroll 4
    for (int k = 0; k < D; k++) {
        const float* Uk = Mt + k * 132 + e0t;
        u64 a[4];
#pragma unroll
        for (int p = 0; p < 4; p++) a[p] = *(const u64*)(Uk + 2 * p);
        const float* Wg = Wt + k * D + tx;
#pragma unroll
        for (int j = 0; j < 4; j++) {
            u64 wp = pack2same(Wg[32 * j]);
#pragma unroll
            for (int p = 0; p < 4; p++) fma2(acc[p][j], a[p], wp);
        }
    }

#pragma unroll
    for (int j = 0; j < 4; j++) {
        int d = tx + 32 * j;
        float bb = lb[d];
#pragma unroll
        for (int p = 0; p < 4; p++) {
            float2 v = unpack2(acc[p][j]);
            int nl = e0t + 2 * p;
#pragma unroll
            for (int hh = 0; hh < 2; hh++) {
                int n1 = n0 + nl + hh;
                if (n1 < N_) {
                    float hv = Ht[d * 132 + nl + hh];   // original h[n][d]
                    float r = hv + (hh ? v.y : v.x) + bb;
                    h[(size_t)n1 * D + d] = r;
                    if (out2) out2[(size_t)n1 * D + d] = r;
                }
            }
        }
    }
}

// =======================================================================
extern "C" void kernel_launch(void* const* d_in, const int* in_sizes, int n_in,
                              void* d_out, int out_size)
{
    const float* z        = (const float*)d_in[0];
    const void*  eidx     = d_in[1];                 // int32 OR int64 — detected on device
    const float* elen     = (const float*)d_in[2];
    const float* eattr    = (const float*)d_in[3];
    const float* emblin_w = (const float*)d_in[4];
    const float* emblin_b = (const float*)d_in[5];
    const float* mlp_w1   = (const float*)d_in[6];
    const float* mlp_b1   = (const float*)d_in[7];
    const float* mlp_w2   = (const float*)d_in[8];
    const float* mlp_b2   = (const float*)d_in[9];
    const float* lin1_w   = (const float*)d_in[10];
    const float* lin2_w   = (const float*)d_in[11];
    const float* lin2_b   = (const float*)d_in[12];
    const float* lin_w    = (const float*)d_in[13];
    const float* lin_b    = (const float*)d_in[14];
    float* out = (float*)d_out;

    const int N_ = in_sizes[0] / (NIN + D);
    const int E_ = in_sizes[2];
    const int L_ = in_sizes[7] / D;   // mlp_b1 is (L, D)

    float *hp, *xfp, *mip, *mp;
    int *srcp, *dstp;
    cudaGetSymbolAddress((void**)&hp,  g_h);
    cudaGetSymbolAddress((void**)&xfp, g_xf);
    cudaGetSymbolAddress((void**)&mip, g_mi);
    cudaGetSymbolAddress((void**)&mp,  g_m);
    cudaGetSymbolAddress((void**)&srcp, g_src);
    cudaGetSymbolAddress((void**)&dstp, g_dst);

    const size_t smemE = (size_t)(D * G + D * D + BE * 132 + D + D + BE) * 4
                       + (size_t)(2 * BE) * 4;                 // 186,880 B
    const size_t smemA = (size_t)(D * D + 128 * 132) * 4;      // 133,120 B
    const size_t smemU = (size_t)(D * D + 2 * 128 * 132) * 4;  // 200,704 B

    cudaFuncSetAttribute(edge_kernel,      cudaFuncAttributeMaxDynamicSharedMemorySize, (int)smemE);
    cudaFuncSetAttribute(node_gemm_kernel, cudaFuncAttributeMaxDynamicSharedMemorySize, (int)smemA);
    cudaFuncSetAttribute(update_kernel,    cudaFuncAttributeMaxDynamicSharedMemorySize, (int)smemU);

    int nsm = 148;
    cudaDeviceGetAttribute(&nsm, cudaDevAttrMultiProcessorCount, 0);

    const int ntiles = (E_ + BE - 1) / BE;
    const int egrid  = (ntiles < nsm) ? ntiles : nsm;
    const int nb     = (N_ + 127) / 128;
    const int elemsN = N_ * D;

    // index conversion with inline dtype detection (once; layer-invariant)
    convert_idx_kernel<<<(E_ + 255) / 256, 256>>>(eidx, E_, N_);

    embed_kernel<<<(elemsN + 255) / 256, 256>>>(z, emblin_w, emblin_b, hp, N_);

    for (int l = 0; l < L_; l++) {
        const float* w1 = mlp_w1 + (size_t)l * D * G;
        const float* b1 = mlp_b1 + (size_t)l * D;
        const float* w2 = mlp_w2 + (size_t)l * D * D;
        const float* b2 = mlp_b2 + (size_t)l * D;
        const float* l1w = lin1_w + (size_t)l * D * D;
        const float* l2w = lin2_w + (size_t)l * D * D;
        const float* l2b = lin2_b + (size_t)l * D;
        const float* lw  = lin_w  + (size_t)l * D * 2 * D;
        const float* lb  = lin_b  + (size_t)l * D;

        // xf = h @ lin1.T, fused with zeroing of mi
        node_gemm_kernel<<<nb, NT, smemA>>>(hp, l1w, nullptr, xfp, N_, 0, mip);
        edge_kernel<<<egrid, NT, smemE>>>(eattr, srcp, dstp, elen, w1, b1, w2, b2,
                                          xfp, mip, E_);
        node_gemm_kernel<<<nb, NT, smemA>>>(mip, l2w, l2b, mp, N_, 1, nullptr);
        update_kernel<<<nb, NT, smemU>>>(hp, mp, lw, lb, N_,
                                         (l == L_ - 1) ? out : nullptr);
    }
}